// round 1
// baseline (speedup 1.0000x reference)
#include <cuda_runtime.h>
#include <cuda_bf16.h>

// Problem constants (fixed dataset): N=50000, E=800000, F=64, U=64, H=8
#define NMAX 50000
#define EMAX 800000
#define NEG_SLOPE 0.2f

// Scratch (static device globals — no runtime allocation allowed)
__device__ float g_h[(size_t)NMAX * 512];     // 102.4 MB: h[n][head*64+u]
__device__ float g_agg[(size_t)NMAX * 512];   // 102.4 MB: normalized aggregate
__device__ float g_asrc[NMAX * 8];
__device__ float g_adst[NMAX * 8];
__device__ int   g_rowptr[NMAX + 1];

// ---------------------------------------------------------------------------
// K0: row_ptr via binary search over sorted src (edges[e][0])
// ---------------------------------------------------------------------------
__global__ void k0_rowptr(const int* __restrict__ edges, int N, int E) {
    int n = blockIdx.x * blockDim.x + threadIdx.x;
    if (n > N) return;
    if (n == N) { g_rowptr[N] = E; return; }
    int lo = 0, hi = E;
    while (lo < hi) {
        int mid = (lo + hi) >> 1;
        if (edges[2 * mid] < n) lo = mid + 1; else hi = mid;
    }
    g_rowptr[n] = lo;
}

// ---------------------------------------------------------------------------
// K1: h[n][c] = sum_f X[n][f] * W'[f][c], W'[f][h*64+u] = W[h][f][u]
// GEMM 50000x64 @ 64x512. W' staged in smem (128KB). 256 thr, 16 rows/chunk.
// Thread computes 4 rows x 8 cols (cols colT*4..+3 and 256+colT*4..+3).
// ---------------------------------------------------------------------------
__global__ void k1_h(const float* __restrict__ X, const float* __restrict__ W, int N) {
    extern __shared__ float smem[];
    float4* Ws4 = (float4*)smem;                  // [64][128] float4 (f, cq)
    float4* Xs4 = (float4*)(smem + 64 * 512);     // [16][16]  float4 (r, kq)
    int t = threadIdx.x;

    // Stage W' : Ws4[f*128 + cq] = W4[(cq>>4)*1024 + f*16 + (cq&15)]
    #pragma unroll
    for (int i = 0; i < 32; i++) {
        int idx = t + i * 256;
        int f = idx >> 7, cq = idx & 127;
        Ws4[idx] = ((const float4*)W)[(cq >> 4) * 1024 + f * 16 + (cq & 15)];
    }
    __syncthreads();

    int colT = t & 63, rowT = t >> 6;
    int nChunks = (N + 15) >> 4;
    for (int ch = blockIdx.x; ch < nChunks; ch += gridDim.x) {
        int n0 = ch * 16;
        // stage X chunk: 16 rows x 16 float4
        {
            int r = t >> 4, kq = t & 15;
            float4 v = make_float4(0.f, 0.f, 0.f, 0.f);
            if (n0 + r < N) v = ((const float4*)X)[(size_t)(n0 + r) * 16 + kq];
            Xs4[r * 16 + kq] = v;
        }
        __syncthreads();

        float acc[4][8];
        #pragma unroll
        for (int i = 0; i < 4; i++)
            #pragma unroll
            for (int j = 0; j < 8; j++) acc[i][j] = 0.f;

        #pragma unroll 4
        for (int k4 = 0; k4 < 16; k4++) {
            float ar[4][4];
            #pragma unroll
            for (int i = 0; i < 4; i++) {
                float4 av = Xs4[(rowT * 4 + i) * 16 + k4];
                ar[i][0] = av.x; ar[i][1] = av.y; ar[i][2] = av.z; ar[i][3] = av.w;
            }
            #pragma unroll
            for (int kk = 0; kk < 4; kk++) {
                float4 b0 = Ws4[(k4 * 4 + kk) * 128 + colT];
                float4 b1 = Ws4[(k4 * 4 + kk) * 128 + 64 + colT];
                #pragma unroll
                for (int i = 0; i < 4; i++) {
                    float a = ar[i][kk];
                    acc[i][0] = fmaf(a, b0.x, acc[i][0]);
                    acc[i][1] = fmaf(a, b0.y, acc[i][1]);
                    acc[i][2] = fmaf(a, b0.z, acc[i][2]);
                    acc[i][3] = fmaf(a, b0.w, acc[i][3]);
                    acc[i][4] = fmaf(a, b1.x, acc[i][4]);
                    acc[i][5] = fmaf(a, b1.y, acc[i][5]);
                    acc[i][6] = fmaf(a, b1.z, acc[i][6]);
                    acc[i][7] = fmaf(a, b1.w, acc[i][7]);
                }
            }
        }
        // store
        #pragma unroll
        for (int i = 0; i < 4; i++) {
            int r = n0 + rowT * 4 + i;
            if (r < N) {
                float4 o0 = make_float4(acc[i][0], acc[i][1], acc[i][2], acc[i][3]);
                float4 o1 = make_float4(acc[i][4], acc[i][5], acc[i][6], acc[i][7]);
                ((float4*)g_h)[(size_t)r * 128 + colT] = o0;
                ((float4*)g_h)[(size_t)r * 128 + 64 + colT] = o1;
            }
        }
        __syncthreads();
    }
}

// ---------------------------------------------------------------------------
// K1b: alpha_src[n][h] = sum_u h[n][h][u]*a[h][u], alpha_dst with a[h][64+u].
// One warp per node; per-lane float4 partials + width-16 shuffle reduction.
// ---------------------------------------------------------------------------
__global__ void k1b_alpha(const float* __restrict__ a, int N) {
    __shared__ float sa[512], sd[512];
    int t = threadIdx.x;
    for (int i = t; i < 512; i += 256) {
        int hh = i >> 6, u = i & 63;
        sa[i] = a[hh * 128 + u];
        sd[i] = a[hh * 128 + 64 + u];
    }
    __syncthreads();
    int w = t >> 5, l = t & 31;
    int n = blockIdx.x * 8 + w;
    if (n >= N) return;

    float ps[4], pd[4];
    #pragma unroll
    for (int q = 0; q < 4; q++) {
        int fidx = l + 32 * q;  // float4 index; channel c = 4*fidx
        float4 hv = ((const float4*)g_h)[(size_t)n * 128 + fidx];
        float4 av = ((const float4*)sa)[fidx];
        float4 dv = ((const float4*)sd)[fidx];
        ps[q] = hv.x * av.x + hv.y * av.y + hv.z * av.z + hv.w * av.w;
        pd[q] = hv.x * dv.x + hv.y * dv.y + hv.z * dv.z + hv.w * dv.w;
    }
    #pragma unroll
    for (int off = 8; off > 0; off >>= 1) {
        #pragma unroll
        for (int q = 0; q < 4; q++) {
            ps[q] += __shfl_down_sync(0xffffffffu, ps[q], off, 16);
            pd[q] += __shfl_down_sync(0xffffffffu, pd[q], off, 16);
        }
    }
    if ((l & 15) == 0) {
        int hb = l >> 4;  // 0 or 1
        #pragma unroll
        for (int q = 0; q < 4; q++) {
            g_asrc[n * 8 + hb + 2 * q] = ps[q];
            g_adst[n * 8 + hb + 2 * q] = pd[q];
        }
    }
}

// ---------------------------------------------------------------------------
// K2: per-node edge aggregation (src sorted -> contiguous segment).
// out_agg[n][c] = (sum_e att_e * h[dst_e][c]) / (sum_e att_e)   per head.
// One 128-thread block per node; thread owns channels 4t..4t+3 (float4).
// ---------------------------------------------------------------------------
__global__ void k2_agg(const int* __restrict__ edges, int N) {
    int n = blockIdx.x;
    int t = threadIdx.x;  // 0..127
    int start = g_rowptr[n], end = g_rowptr[n + 1];

    __shared__ float asrc[8];
    __shared__ float attsum[8];
    __shared__ float att_s[16][8];
    __shared__ int   dst_s[16];

    if (t < 8) { asrc[t] = g_asrc[n * 8 + t]; attsum[t] = 0.f; }
    __syncthreads();

    float4 acc = make_float4(0.f, 0.f, 0.f, 0.f);
    int head = t >> 4;  // (4t)/64

    for (int e0 = start; e0 < end; e0 += 16) {
        int cnt = min(16, end - e0);
        if (t < cnt * 8) {
            int ei = t >> 3, hh = t & 7;
            int d = edges[2 * (e0 + ei) + 1];
            if (hh == 0) dst_s[ei] = d;
            float s = asrc[hh] + g_adst[d * 8 + hh];
            s = s > 0.f ? s : NEG_SLOPE * s;            // leaky_relu
            s = fminf(2.f, fmaxf(-2.f, s));             // clip
            float av = __expf(s);
            att_s[ei][hh] = av;
            atomicAdd(&attsum[hh], av);
        }
        __syncthreads();
        #pragma unroll 2
        for (int i = 0; i < cnt; i++) {
            int d = dst_s[i];
            float av = att_s[i][head];
            float4 hv = ((const float4*)g_h)[(size_t)d * 128 + t];
            acc.x = fmaf(av, hv.x, acc.x);
            acc.y = fmaf(av, hv.y, acc.y);
            acc.z = fmaf(av, hv.z, acc.z);
            acc.w = fmaf(av, hv.w, acc.w);
        }
        __syncthreads();
    }

    float s = attsum[head];
    float inv = (s > 0.f) ? (1.f / s) : 0.f;   // empty segment -> zeros
    float4 o = make_float4(acc.x * inv, acc.y * inv, acc.z * inv, acc.w * inv);
    ((float4*)g_agg)[(size_t)n * 128 + t] = o;
}

// ---------------------------------------------------------------------------
// K3: out = leaky_relu(agg (N x 512) @ M (512 x 64)).  M staged in smem
// (128KB). 256 thr; 32 rows/chunk; thread computes 8 rows x 1 col.
// ---------------------------------------------------------------------------
__global__ void k3_merge(const float* __restrict__ M, float* __restrict__ out, int N) {
    extern __shared__ float smem[];
    float*  Ms  = smem;                        // [512][64]
    float4* Ms4 = (float4*)smem;
    float4* As4 = (float4*)(smem + 512 * 64);  // [32][128] float4
    int t = threadIdx.x;

    #pragma unroll
    for (int i = 0; i < 32; i++) Ms4[t + i * 256] = ((const float4*)M)[t + i * 256];
    __syncthreads();

    int colJ = t & 63, rowT = t >> 6;
    int nChunks = (N + 31) >> 5;
    for (int ch = blockIdx.x; ch < nChunks; ch += gridDim.x) {
        int n0 = ch * 32;
        #pragma unroll
        for (int i = 0; i < 16; i++) {
            int idx = t + i * 256;      // r*128 + kq
            int r = idx >> 7;
            float4 v = make_float4(0.f, 0.f, 0.f, 0.f);
            if (n0 + r < N) v = ((const float4*)g_agg)[(size_t)(n0 + r) * 128 + (idx & 127)];
            As4[idx] = v;
        }
        __syncthreads();

        float acc[8];
        #pragma unroll
        for (int i = 0; i < 8; i++) acc[i] = 0.f;

        #pragma unroll 8
        for (int k4 = 0; k4 < 128; k4++) {
            float b0 = Ms[(4 * k4 + 0) * 64 + colJ];
            float b1 = Ms[(4 * k4 + 1) * 64 + colJ];
            float b2 = Ms[(4 * k4 + 2) * 64 + colJ];
            float b3 = Ms[(4 * k4 + 3) * 64 + colJ];
            #pragma unroll
            for (int i = 0; i < 8; i++) {
                float4 av = As4[(rowT * 8 + i) * 128 + k4];
                acc[i] = fmaf(av.x, b0, acc[i]);
                acc[i] = fmaf(av.y, b1, acc[i]);
                acc[i] = fmaf(av.z, b2, acc[i]);
                acc[i] = fmaf(av.w, b3, acc[i]);
            }
        }
        #pragma unroll
        for (int i = 0; i < 8; i++) {
            int r = n0 + rowT * 8 + i;
            if (r < N) {
                float v = acc[i];
                out[(size_t)r * 64 + colJ] = v > 0.f ? v : NEG_SLOPE * v;
            }
        }
        __syncthreads();
    }
}

// ---------------------------------------------------------------------------
extern "C" void kernel_launch(void* const* d_in, const int* in_sizes, int n_in,
                              void* d_out, int out_size) {
    const float* X  = (const float*)d_in[0];   // atom_features (N,64)
    const int*   Ed = (const int*)d_in[1];     // edges (E,2)
    const float* W  = (const float*)d_in[2];   // (8,64,64)
    const float* A  = (const float*)d_in[3];   // (8,128,1)
    const float* M  = (const float*)d_in[4];   // (512,64)
    float* out = (float*)d_out;                // (N,64)

    int N = in_sizes[0] / 64;
    int E = in_sizes[1] / 2;

    static bool attr_set = false;
    if (!attr_set) {
        cudaFuncSetAttribute(k1_h, cudaFuncAttributeMaxDynamicSharedMemorySize, 135168);
        cudaFuncSetAttribute(k3_merge, cudaFuncAttributeMaxDynamicSharedMemorySize, 196608);
        attr_set = true;
    }

    k0_rowptr<<<(N + 1 + 255) / 256, 256>>>(Ed, N, E);
    k1_h<<<296, 256, 135168>>>(X, W, N);
    k1b_alpha<<<(N + 7) / 8, 256>>>(A, N);
    k2_agg<<<N, 128>>>(Ed, N);
    k3_merge<<<296, 256, 196608>>>(M, out, N);
}

// round 2
// speedup vs baseline: 1.6804x; 1.6804x over previous
#include <cuda_runtime.h>
#include <cuda_bf16.h>

// Fixed dataset: N=50000, E=800000, F=64, U=64, H=8
#define NMAX 50000
#define NEG_SLOPE 0.2f
#define DEGCAP 96

// Scratch
__device__ float g_p[(size_t)NMAX * 512];    // 102.4 MB: p[n][c*8+h] = (x_n @ W_h @ M_h)[c]
__device__ float g_asrc[NMAX * 8];
__device__ float g_adst[NMAX * 8];
__device__ int   g_rowptr[NMAX + 1];
__device__ float g_wmt[64 * 512];            // WMt[f][c*8+h] = (W_h @ M_h)[f][c]
__device__ float g_aw[64 * 16];              // [f][side*8+h] = (W_h @ a[h,side])[f]

// ---------------------------------------------------------------------------
// K0: row_ptr via binary search over sorted src
// ---------------------------------------------------------------------------
__global__ void k0_rowptr(const int* __restrict__ edges, int N, int E) {
    int n = blockIdx.x * blockDim.x + threadIdx.x;
    if (n > N) return;
    if (n == N) { g_rowptr[N] = E; return; }
    int lo = 0, hi = E;
    while (lo < hi) {
        int mid = (lo + hi) >> 1;
        if (edges[2 * mid] < n) lo = mid + 1; else hi = mid;
    }
    g_rowptr[n] = lo;
}

// ---------------------------------------------------------------------------
// KPRE: fold weights.
//   g_wmt[f][c*8+h] = sum_u W[h,f,u] * M[h*64+u, c]
//   g_aw [f][s*8+h] = sum_u W[h,f,u] * a[h*128 + s*64 + u]
// ---------------------------------------------------------------------------
__global__ void kpre(const float* __restrict__ W, const float* __restrict__ a,
                     const float* __restrict__ M) {
    int idx = blockIdx.x * blockDim.x + threadIdx.x;
    if (idx < 64 * 512) {
        int f = idx >> 9, col = idx & 511;
        int c = col >> 3, h = col & 7;
        const float* wp = W + h * 4096 + f * 64;
        const float* mp = M + (h * 64) * 64 + c;
        float s = 0.f;
        #pragma unroll 8
        for (int u = 0; u < 64; u++) s = fmaf(wp[u], mp[u * 64], s);
        g_wmt[f * 512 + col] = s;
    } else {
        int j = idx - 64 * 512;
        if (j < 1024) {
            int f = j >> 4, q = j & 15;
            int h = q & 7, side = q >> 3;
            const float* wp = W + h * 4096 + f * 64;
            const float* ap = a + h * 128 + side * 64;
            float s = 0.f;
            #pragma unroll 8
            for (int u = 0; u < 64; u++) s = fmaf(wp[u], ap[u], s);
            g_aw[f * 16 + q] = s;
        }
    }
}

// ---------------------------------------------------------------------------
// KALPHA: alphas = X @ g_aw  (N x 64 @ 64 x 16). 256 thr = 16 nodes x 16 cols.
// ---------------------------------------------------------------------------
__global__ void kalpha(const float* __restrict__ X, int N) {
    __shared__ float Xs[16 * 64];
    __shared__ float aws[64 * 16];
    int t = threadIdx.x;
    ((float4*)aws)[t] = ((const float4*)g_aw)[t];
    int n0 = blockIdx.x * 16;
    int r = t >> 4, q = t & 15;
    {
        float4 v = make_float4(0.f, 0.f, 0.f, 0.f);
        if (n0 + r < N) v = ((const float4*)X)[(size_t)(n0 + r) * 16 + q];
        ((float4*)Xs)[r * 16 + q] = v;
    }
    __syncthreads();
    float s = 0.f;
    #pragma unroll 16
    for (int f = 0; f < 64; f++) s = fmaf(Xs[r * 64 + f], aws[f * 16 + q], s);
    int n = n0 + r;
    if (n < N) {
        int h = q & 7;
        if (q < 8) g_asrc[n * 8 + h] = s;
        else       g_adst[n * 8 + h] = s;
    }
}

// ---------------------------------------------------------------------------
// K1P: p = X @ WMt  (N x 64 @ 64 x 512). Each block owns one 256-col half of
// WMt in smem (64 KB) + 16-row X tiles (4 KB) -> 3 blocks/SM.
// Thread computes 4 rows x 4 cols (float4).
// ---------------------------------------------------------------------------
__global__ void k1p(const float* __restrict__ X, int N) {
    extern __shared__ float smem[];
    float4* Ws4 = (float4*)smem;              // [64][64] float4
    float4* Xs4 = (float4*)(smem + 64 * 256); // [16][16] float4
    int t = threadIdx.x;
    int half = blockIdx.x & 1;

    const float4* wmt4 = (const float4*)g_wmt;  // row stride 128 float4
    #pragma unroll
    for (int i = 0; i < 16; i++) {
        int idx = t + i * 256;
        int f = idx >> 6, cq = idx & 63;
        Ws4[idx] = wmt4[f * 128 + half * 64 + cq];
    }
    __syncthreads();

    int colT = t & 63, rowT = t >> 6;
    int nChunks = (N + 15) >> 4;
    int step = gridDim.x >> 1;
    for (int ch = (blockIdx.x >> 1); ch < nChunks; ch += step) {
        int n0 = ch * 16;
        {
            int r = t >> 4, kq = t & 15;
            float4 v = make_float4(0.f, 0.f, 0.f, 0.f);
            if (n0 + r < N) v = ((const float4*)X)[(size_t)(n0 + r) * 16 + kq];
            Xs4[r * 16 + kq] = v;
        }
        __syncthreads();

        float acc[4][4];
        #pragma unroll
        for (int i = 0; i < 4; i++)
            #pragma unroll
            for (int j = 0; j < 4; j++) acc[i][j] = 0.f;

        #pragma unroll 4
        for (int k4 = 0; k4 < 16; k4++) {
            float ar[4][4];
            #pragma unroll
            for (int i = 0; i < 4; i++) {
                float4 av = Xs4[(rowT * 4 + i) * 16 + k4];
                ar[i][0] = av.x; ar[i][1] = av.y; ar[i][2] = av.z; ar[i][3] = av.w;
            }
            #pragma unroll
            for (int kk = 0; kk < 4; kk++) {
                float4 b = Ws4[(k4 * 4 + kk) * 64 + colT];
                #pragma unroll
                for (int i = 0; i < 4; i++) {
                    float a = ar[i][kk];
                    acc[i][0] = fmaf(a, b.x, acc[i][0]);
                    acc[i][1] = fmaf(a, b.y, acc[i][1]);
                    acc[i][2] = fmaf(a, b.z, acc[i][2]);
                    acc[i][3] = fmaf(a, b.w, acc[i][3]);
                }
            }
        }
        #pragma unroll
        for (int i = 0; i < 4; i++) {
            int r = n0 + rowT * 4 + i;
            if (r < N) {
                ((float4*)g_p)[(size_t)r * 128 + half * 64 + colT] =
                    make_float4(acc[i][0], acc[i][1], acc[i][2], acc[i][3]);
            }
        }
        __syncthreads();
    }
}

// ---------------------------------------------------------------------------
// K2N: fused attention + aggregation + merge.
// out[n][c] = leaky( sum_h inv_s[h] * sum_e att[e,h] * p[dst_e][c*8+h] )
// One 128-thread block per node. Thread t: channel c = t>>1, head-half hb=t&1
// (4 heads per float4). Pair-combined via shfl_xor(1).
// ---------------------------------------------------------------------------
__global__ void k2n(const int* __restrict__ edges, float* __restrict__ out, int N) {
    __shared__ float asrc[8];
    __shared__ float attsum[8];
    __shared__ float inv_s[8];
    __shared__ float att_s[DEGCAP * 8];
    __shared__ int   dst_s[DEGCAP];

    int n = blockIdx.x;
    int t = threadIdx.x;
    int start = g_rowptr[n], end = g_rowptr[n + 1];
    int deg = end - start;

    if (t < 8) { asrc[t] = g_asrc[n * 8 + t]; attsum[t] = 0.f; }
    __syncthreads();

    float4 acc = make_float4(0.f, 0.f, 0.f, 0.f);
    int hb = t & 1;
    int ei = t >> 3, hh = t & 7;

    if (deg <= DEGCAP) {
        // Phase 1: raw attention into smem + per-head sums
        float psum = 0.f;
        for (int e0 = 0; e0 < deg; e0 += 16) {
            bool valid = (e0 + ei) < deg;
            float av = 0.f;
            if (valid) {
                int d = edges[2 * (start + e0 + ei) + 1];
                if (hh == 0) dst_s[e0 + ei] = d;
                float s = asrc[hh] + g_adst[d * 8 + hh];
                s = s > 0.f ? s : NEG_SLOPE * s;
                s = fminf(2.f, fmaxf(-2.f, s));
                av = __expf(s);
                att_s[(e0 + ei) * 8 + hh] = av;
            }
            psum += av;
        }
        psum += __shfl_down_sync(0xffffffffu, psum, 16);
        psum += __shfl_down_sync(0xffffffffu, psum, 8);
        if ((t & 31) < 8) atomicAdd(&attsum[hh], psum);
        __syncthreads();
        if (t < 8) inv_s[t] = attsum[t] > 0.f ? 1.f / attsum[t] : 0.f;
        __syncthreads();
        for (int i = t; i < deg * 8; i += 128) att_s[i] *= inv_s[i & 7];
        __syncthreads();

        // Phase 2: gather p[dst] with normalized weights
        #pragma unroll 4
        for (int i = 0; i < deg; i++) {
            float4 a4 = ((const float4*)att_s)[i * 2 + hb];
            float4 pv = ((const float4*)g_p)[(size_t)dst_s[i] * 128 + t];
            acc.x = fmaf(a4.x, pv.x, acc.x);
            acc.y = fmaf(a4.y, pv.y, acc.y);
            acc.z = fmaf(a4.z, pv.z, acc.z);
            acc.w = fmaf(a4.w, pv.w, acc.w);
        }
    } else {
        // Rare fallback (deg > DEGCAP): sum pass with recompute
        float psum = 0.f;
        for (int e0 = 0; e0 < deg; e0 += 16) {
            bool valid = (e0 + ei) < deg;
            float av = 0.f;
            if (valid) {
                int d = edges[2 * (start + e0 + ei) + 1];
                float s = asrc[hh] + g_adst[d * 8 + hh];
                s = s > 0.f ? s : NEG_SLOPE * s;
                s = fminf(2.f, fmaxf(-2.f, s));
                av = __expf(s);
            }
            psum += av;
        }
        psum += __shfl_down_sync(0xffffffffu, psum, 16);
        psum += __shfl_down_sync(0xffffffffu, psum, 8);
        if ((t & 31) < 8) atomicAdd(&attsum[hh], psum);
        __syncthreads();
        if (t < 8) inv_s[t] = attsum[t] > 0.f ? 1.f / attsum[t] : 0.f;
        __syncthreads();

        for (int e0 = 0; e0 < deg; e0 += 16) {
            int cnt = min(16, deg - e0);
            if (t < cnt * 8) {
                int d = edges[2 * (start + e0 + ei) + 1];
                if (hh == 0) dst_s[ei] = d;
                float s = asrc[hh] + g_adst[d * 8 + hh];
                s = s > 0.f ? s : NEG_SLOPE * s;
                s = fminf(2.f, fmaxf(-2.f, s));
                att_s[ei * 8 + hh] = __expf(s) * inv_s[hh];
            }
            __syncthreads();
            #pragma unroll 2
            for (int i = 0; i < cnt; i++) {
                float4 a4 = ((const float4*)att_s)[i * 2 + hb];
                float4 pv = ((const float4*)g_p)[(size_t)dst_s[i] * 128 + t];
                acc.x = fmaf(a4.x, pv.x, acc.x);
                acc.y = fmaf(a4.y, pv.y, acc.y);
                acc.z = fmaf(a4.z, pv.z, acc.z);
                acc.w = fmaf(a4.w, pv.w, acc.w);
            }
            __syncthreads();
        }
    }

    float v = acc.x + acc.y + acc.z + acc.w;
    v += __shfl_xor_sync(0xffffffffu, v, 1);
    if ((t & 1) == 0) {
        int c = t >> 1;
        out[(size_t)n * 64 + c] = v > 0.f ? v : NEG_SLOPE * v;
    }
}

// ---------------------------------------------------------------------------
extern "C" void kernel_launch(void* const* d_in, const int* in_sizes, int n_in,
                              void* d_out, int out_size) {
    const float* X  = (const float*)d_in[0];   // atom_features (N,64)
    const int*   Ed = (const int*)d_in[1];     // edges (E,2)
    const float* W  = (const float*)d_in[2];   // (8,64,64)
    const float* A  = (const float*)d_in[3];   // (8,128,1)
    const float* M  = (const float*)d_in[4];   // (512,64)
    float* out = (float*)d_out;                // (N,64)

    int N = in_sizes[0] / 64;
    int E = in_sizes[1] / 2;

    static bool attr_set = false;
    if (!attr_set) {
        cudaFuncSetAttribute(k1p, cudaFuncAttributeMaxDynamicSharedMemorySize, 69632);
        attr_set = true;
    }

    k0_rowptr<<<(N + 1 + 255) / 256, 256>>>(Ed, N, E);
    kpre<<<132, 256>>>(W, A, M);
    kalpha<<<(N + 15) / 16, 256>>>(X, N);
    k1p<<<444, 256, 69632>>>(X, N);
    k2n<<<N, 128>>>(Ed, out, N);
}

// round 15
// speedup vs baseline: 2.1572x; 1.2837x over previous
#include <cuda_runtime.h>
#include <cuda_fp16.h>
#include <cuda_bf16.h>

// Fixed dataset: N=50000, E=800000, F=64, U=64, H=8
#define NMAX 50000
#define NEG_SLOPE 0.2f
#define DEGCAP 96

// Scratch
__device__ __half g_ph[(size_t)NMAX * 512];  // 51.2 MB: p[n][c*8+h] fp16
__device__ float g_asrc[NMAX * 8];
__device__ float g_adst[NMAX * 8];
__device__ int   g_rowptr[NMAX + 1];
__device__ float g_wmt[64 * 512];            // WMt[f][c*8+h] = (W_h @ M_h)[f][c]
__device__ float g_aw[64 * 16];              // [f][side*8+h] = (W_h @ a[h,side])[f]

// ---------------------------------------------------------------------------
// K0: row_ptr via binary search over sorted src
// ---------------------------------------------------------------------------
__global__ void k0_rowptr(const int* __restrict__ edges, int N, int E) {
    int n = blockIdx.x * blockDim.x + threadIdx.x;
    if (n > N) return;
    if (n == N) { g_rowptr[N] = E; return; }
    int lo = 0, hi = E;
    while (lo < hi) {
        int mid = (lo + hi) >> 1;
        if (edges[2 * mid] < n) lo = mid + 1; else hi = mid;
    }
    g_rowptr[n] = lo;
}

// ---------------------------------------------------------------------------
// KPRE: fold weights.
//   g_wmt[f][c*8+h] = sum_u W[h,f,u] * M[h*64+u, c]
//   g_aw [f][s*8+h] = sum_u W[h,f,u] * a[h*128 + s*64 + u]
// ---------------------------------------------------------------------------
__global__ void kpre(const float* __restrict__ W, const float* __restrict__ a,
                     const float* __restrict__ M) {
    int idx = blockIdx.x * blockDim.x + threadIdx.x;
    if (idx < 64 * 512) {
        int f = idx >> 9, col = idx & 511;
        int c = col >> 3, h = col & 7;
        const float* wp = W + h * 4096 + f * 64;
        const float* mp = M + (h * 64) * 64 + c;
        float s = 0.f;
        #pragma unroll 8
        for (int u = 0; u < 64; u++) s = fmaf(wp[u], mp[u * 64], s);
        g_wmt[f * 512 + col] = s;
    } else {
        int j = idx - 64 * 512;
        if (j < 1024) {
            int f = j >> 4, q = j & 15;
            int h = q & 7, side = q >> 3;
            const float* wp = W + h * 4096 + f * 64;
            const float* ap = a + h * 128 + side * 64;
            float s = 0.f;
            #pragma unroll 8
            for (int u = 0; u < 64; u++) s = fmaf(wp[u], ap[u], s);
            g_aw[f * 16 + q] = s;
        }
    }
}

// ---------------------------------------------------------------------------
// KALPHA: alphas = X @ g_aw  (N x 64 @ 64 x 16). 256 thr = 16 nodes x 16 cols.
// ---------------------------------------------------------------------------
__global__ void kalpha(const float* __restrict__ X, int N) {
    __shared__ float Xs[16 * 64];
    __shared__ float aws[64 * 16];
    int t = threadIdx.x;
    ((float4*)aws)[t] = ((const float4*)g_aw)[t];
    int n0 = blockIdx.x * 16;
    int r = t >> 4, q = t & 15;
    {
        float4 v = make_float4(0.f, 0.f, 0.f, 0.f);
        if (n0 + r < N) v = ((const float4*)X)[(size_t)(n0 + r) * 16 + q];
        ((float4*)Xs)[r * 16 + q] = v;
    }
    __syncthreads();
    float s = 0.f;
    #pragma unroll 16
    for (int f = 0; f < 64; f++) s = fmaf(Xs[r * 64 + f], aws[f * 16 + q], s);
    int n = n0 + r;
    if (n < N) {
        int h = q & 7;
        if (q < 8) g_asrc[n * 8 + h] = s;
        else       g_adst[n * 8 + h] = s;
    }
}

// ---------------------------------------------------------------------------
// K1P: p = X @ WMt  (N x 64 @ 64 x 512), fp16 output.
// Block owns one 256-col half of WMt in smem (64KB) + 32-row X tiles (8KB).
// Thread computes 8 rows x 4 cols.
// ---------------------------------------------------------------------------
__global__ void k1p(const float* __restrict__ X, int N) {
    extern __shared__ float smem[];
    float4* Ws4 = (float4*)smem;              // [64][64] float4
    float4* Xs4 = (float4*)(smem + 64 * 256); // [32][16] float4
    int t = threadIdx.x;
    int half_b = blockIdx.x & 1;

    const float4* wmt4 = (const float4*)g_wmt;  // row stride 128 float4
    #pragma unroll
    for (int i = 0; i < 16; i++) {
        int idx = t + i * 256;
        int f = idx >> 6, cq = idx & 63;
        Ws4[idx] = wmt4[f * 128 + half_b * 64 + cq];
    }
    __syncthreads();

    int colT = t & 63, rowT = t >> 6;   // rowT 0..3, 8 rows each
    int nChunks = (N + 31) >> 5;
    int step = gridDim.x >> 1;
    for (int ch = (blockIdx.x >> 1); ch < nChunks; ch += step) {
        int n0 = ch * 32;
        #pragma unroll
        for (int i = 0; i < 2; i++) {
            int idx = t + i * 256;      // over 512 float4 = 32 rows x 16
            int r = idx >> 4, kq = idx & 15;
            float4 v = make_float4(0.f, 0.f, 0.f, 0.f);
            if (n0 + r < N) v = ((const float4*)X)[(size_t)(n0 + r) * 16 + kq];
            Xs4[idx] = v;
        }
        __syncthreads();

        float acc[8][4];
        #pragma unroll
        for (int i = 0; i < 8; i++)
            #pragma unroll
            for (int j = 0; j < 4; j++) acc[i][j] = 0.f;

        #pragma unroll 2
        for (int k4 = 0; k4 < 16; k4++) {
            float4 ar[8];
            #pragma unroll
            for (int i = 0; i < 8; i++) ar[i] = Xs4[(rowT * 8 + i) * 16 + k4];
            #pragma unroll
            for (int kk = 0; kk < 4; kk++) {
                float4 b = Ws4[(k4 * 4 + kk) * 64 + colT];
                #pragma unroll
                for (int i = 0; i < 8; i++) {
                    float a = (kk == 0) ? ar[i].x : (kk == 1) ? ar[i].y
                             : (kk == 2) ? ar[i].z : ar[i].w;
                    acc[i][0] = fmaf(a, b.x, acc[i][0]);
                    acc[i][1] = fmaf(a, b.y, acc[i][1]);
                    acc[i][2] = fmaf(a, b.z, acc[i][2]);
                    acc[i][3] = fmaf(a, b.w, acc[i][3]);
                }
            }
        }
        int colbase = half_b * 64 + colT;   // uint2 index within 128-wide row
        #pragma unroll
        for (int i = 0; i < 8; i++) {
            int r = n0 + rowT * 8 + i;
            if (r < N) {
                __half2 h01 = __floats2half2_rn(acc[i][0], acc[i][1]);
                __half2 h23 = __floats2half2_rn(acc[i][2], acc[i][3]);
                uint2 st;
                st.x = *(unsigned int*)&h01;
                st.y = *(unsigned int*)&h23;
                ((uint2*)g_ph)[(size_t)r * 128 + colbase] = st;
            }
        }
        __syncthreads();
    }
}

// ---------------------------------------------------------------------------
// K2N: fused attention + aggregation + merge. fp16 p gathers.
// out[n][c] = leaky( sum_h inv_s[h] * sum_e att[e,h] * p[dst_e][c*8+h] )
// 128-thread block per node. Thread t: channel c=t>>1, head-half hb=t&1.
// ---------------------------------------------------------------------------
__global__ void k2n(const int* __restrict__ edges, float* __restrict__ out, int N) {
    __shared__ float asrc[8];
    __shared__ float attsum[8];
    __shared__ float inv_s[8];
    __shared__ float att_s[DEGCAP * 8];
    __shared__ int   dst_s[DEGCAP];

    int n = blockIdx.x;
    int t = threadIdx.x;
    int start = g_rowptr[n], end = g_rowptr[n + 1];
    int deg = end - start;

    if (t < 8) { asrc[t] = g_asrc[n * 8 + t]; attsum[t] = 0.f; }
    __syncthreads();

    float4 acc = make_float4(0.f, 0.f, 0.f, 0.f);
    int hb = t & 1;
    int ei = t >> 3, hh = t & 7;

    if (deg <= DEGCAP) {
        float psum = 0.f;
        for (int e0 = 0; e0 < deg; e0 += 16) {
            bool valid = (e0 + ei) < deg;
            float av = 0.f;
            if (valid) {
                int d = edges[2 * (start + e0 + ei) + 1];
                if (hh == 0) dst_s[e0 + ei] = d;
                float s = asrc[hh] + g_adst[d * 8 + hh];
                s = s > 0.f ? s : NEG_SLOPE * s;
                s = fminf(2.f, fmaxf(-2.f, s));
                av = __expf(s);
                att_s[(e0 + ei) * 8 + hh] = av;
            }
            psum += av;
        }
        psum += __shfl_down_sync(0xffffffffu, psum, 16);
        psum += __shfl_down_sync(0xffffffffu, psum, 8);
        if ((t & 31) < 8) atomicAdd(&attsum[hh], psum);
        __syncthreads();
        if (t < 8) inv_s[t] = attsum[t] > 0.f ? 1.f / attsum[t] : 0.f;
        __syncthreads();
        for (int i = t; i < deg * 8; i += 128) att_s[i] *= inv_s[i & 7];
        __syncthreads();

        #pragma unroll 4
        for (int i = 0; i < deg; i++) {
            float4 a4 = ((const float4*)att_s)[i * 2 + hb];
            uint2 pv = ((const uint2*)g_ph)[(size_t)dst_s[i] * 128 + t];
            float2 f01 = __half22float2(*(__half2*)&pv.x);
            float2 f23 = __half22float2(*(__half2*)&pv.y);
            acc.x = fmaf(a4.x, f01.x, acc.x);
            acc.y = fmaf(a4.y, f01.y, acc.y);
            acc.z = fmaf(a4.z, f23.x, acc.z);
            acc.w = fmaf(a4.w, f23.y, acc.w);
        }
    } else {
        // Rare fallback (deg > DEGCAP)
        float psum = 0.f;
        for (int e0 = 0; e0 < deg; e0 += 16) {
            bool valid = (e0 + ei) < deg;
            float av = 0.f;
            if (valid) {
                int d = edges[2 * (start + e0 + ei) + 1];
                float s = asrc[hh] + g_adst[d * 8 + hh];
                s = s > 0.f ? s : NEG_SLOPE * s;
                s = fminf(2.f, fmaxf(-2.f, s));
                av = __expf(s);
            }
            psum += av;
        }
        psum += __shfl_down_sync(0xffffffffu, psum, 16);
        psum += __shfl_down_sync(0xffffffffu, psum, 8);
        if ((t & 31) < 8) atomicAdd(&attsum[hh], psum);
        __syncthreads();
        if (t < 8) inv_s[t] = attsum[t] > 0.f ? 1.f / attsum[t] : 0.f;
        __syncthreads();

        for (int e0 = 0; e0 < deg; e0 += 16) {
            int cnt = min(16, deg - e0);
            if (t < cnt * 8) {
                int d = edges[2 * (start + e0 + ei) + 1];
                if (hh == 0) dst_s[ei] = d;
                float s = asrc[hh] + g_adst[d * 8 + hh];
                s = s > 0.f ? s : NEG_SLOPE * s;
                s = fminf(2.f, fmaxf(-2.f, s));
                att_s[ei * 8 + hh] = __expf(s) * inv_s[hh];
            }
            __syncthreads();
            #pragma unroll 2
            for (int i = 0; i < cnt; i++) {
                float4 a4 = ((const float4*)att_s)[i * 2 + hb];
                uint2 pv = ((const uint2*)g_ph)[(size_t)dst_s[i] * 128 + t];
                float2 f01 = __half22float2(*(__half2*)&pv.x);
                float2 f23 = __half22float2(*(__half2*)&pv.y);
                acc.x = fmaf(a4.x, f01.x, acc.x);
                acc.y = fmaf(a4.y, f01.y, acc.y);
                acc.z = fmaf(a4.z, f23.x, acc.z);
                acc.w = fmaf(a4.w, f23.y, acc.w);
            }
            __syncthreads();
        }
    }

    float v = acc.x + acc.y + acc.z + acc.w;
    v += __shfl_xor_sync(0xffffffffu, v, 1);
    if ((t & 1) == 0) {
        int c = t >> 1;
        out[(size_t)n * 64 + c] = v > 0.f ? v : NEG_SLOPE * v;
    }
}

// ---------------------------------------------------------------------------
extern "C" void kernel_launch(void* const* d_in, const int* in_sizes, int n_in,
                              void* d_out, int out_size) {
    const float* X  = (const float*)d_in[0];   // atom_features (N,64)
    const int*   Ed = (const int*)d_in[1];     // edges (E,2)
    const float* W  = (const float*)d_in[2];   // (8,64,64)
    const float* A  = (const float*)d_in[3];   // (8,128,1)
    const float* M  = (const float*)d_in[4];   // (512,64)
    float* out = (float*)d_out;                // (N,64)

    int N = in_sizes[0] / 64;
    int E = in_sizes[1] / 2;

    static bool attr_set = false;
    if (!attr_set) {
        cudaFuncSetAttribute(k1p, cudaFuncAttributeMaxDynamicSharedMemorySize, 73728);
        attr_set = true;
    }

    k0_rowptr<<<(N + 1 + 255) / 256, 256>>>(Ed, N, E);
    kpre<<<132, 256>>>(W, A, M);
    kalpha<<<(N + 15) / 16, 256>>>(X, N);
    k1p<<<444, 256, 73728>>>(X, N);
    k2n<<<N, 128>>>(Ed, out, N);
}

// round 16
// speedup vs baseline: 2.5400x; 1.1774x over previous
#include <cuda_runtime.h>
#include <cuda_fp16.h>
#include <cuda_bf16.h>

// Fixed dataset: N=50000, E=800000, F=64, U=64, H=8
#define NMAX 50000
#define NEG_SLOPE 0.2f
#define DEGCAP 96

// Scratch
__device__ __half g_ph[(size_t)NMAX * 512];  // 51.2 MB: p[n][c*8+h] fp16
__device__ float g_asrc[NMAX * 8];
__device__ float g_adst[NMAX * 8];
__device__ int   g_rowptr[NMAX + 1];
__device__ float g_wmt[64 * 512];            // WMt[f][c*8+h] = (W_h @ M_h)[f][c]
__device__ float g_aw[64 * 16];              // [f][side*8+h] = (W_h @ a[h,side])[f]

// ---------------------------------------------------------------------------
// K0: row_ptr via binary search over sorted src
// ---------------------------------------------------------------------------
__global__ void k0_rowptr(const int* __restrict__ edges, int N, int E) {
    int n = blockIdx.x * blockDim.x + threadIdx.x;
    if (n > N) return;
    if (n == N) { g_rowptr[N] = E; return; }
    int lo = 0, hi = E;
    while (lo < hi) {
        int mid = (lo + hi) >> 1;
        if (edges[2 * mid] < n) lo = mid + 1; else hi = mid;
    }
    g_rowptr[n] = lo;
}

// ---------------------------------------------------------------------------
// KPRE: fold weights.
// ---------------------------------------------------------------------------
__global__ void kpre(const float* __restrict__ W, const float* __restrict__ a,
                     const float* __restrict__ M) {
    int idx = blockIdx.x * blockDim.x + threadIdx.x;
    if (idx < 64 * 512) {
        int f = idx >> 9, col = idx & 511;
        int c = col >> 3, h = col & 7;
        const float* wp = W + h * 4096 + f * 64;
        const float* mp = M + (h * 64) * 64 + c;
        float s = 0.f;
        #pragma unroll 8
        for (int u = 0; u < 64; u++) s = fmaf(wp[u], mp[u * 64], s);
        g_wmt[f * 512 + col] = s;
    } else {
        int j = idx - 64 * 512;
        if (j < 1024) {
            int f = j >> 4, q = j & 15;
            int h = q & 7, side = q >> 3;
            const float* wp = W + h * 4096 + f * 64;
            const float* ap = a + h * 128 + side * 64;
            float s = 0.f;
            #pragma unroll 8
            for (int u = 0; u < 64; u++) s = fmaf(wp[u], ap[u], s);
            g_aw[f * 16 + q] = s;
        }
    }
}

// ---------------------------------------------------------------------------
// KALPHA: alphas = X @ g_aw  (N x 64 @ 64 x 16). fp32 path (unchanged).
// ---------------------------------------------------------------------------
__global__ void kalpha(const float* __restrict__ X, int N) {
    __shared__ float Xs[16 * 64];
    __shared__ float aws[64 * 16];
    int t = threadIdx.x;
    ((float4*)aws)[t] = ((const float4*)g_aw)[t];
    int n0 = blockIdx.x * 16;
    int r = t >> 4, q = t & 15;
    {
        float4 v = make_float4(0.f, 0.f, 0.f, 0.f);
        if (n0 + r < N) v = ((const float4*)X)[(size_t)(n0 + r) * 16 + q];
        ((float4*)Xs)[r * 16 + q] = v;
    }
    __syncthreads();
    float s = 0.f;
    #pragma unroll 16
    for (int f = 0; f < 64; f++) s = fmaf(Xs[r * 64 + f], aws[f * 16 + q], s);
    int n = n0 + r;
    if (n < N) {
        int h = q & 7;
        if (q < 8) g_asrc[n * 8 + h] = s;
        else       g_adst[n * 8 + h] = s;
    }
}

// ---------------------------------------------------------------------------
// K1P_MMA: p = X @ WMt via tensor cores (mma.sync m16n8k16 f16->f32).
// smem: Wt[512][72] fp16 (WMt transposed, padded) + Xs[128][72] fp16.
// Block = 256 thr = 8 warps; each warp owns 16 rows of a 128-row chunk.
// Per warp: loop 8 n-chunks of 64 cols = 8 subtiles x 4 k-steps of mma.
// ---------------------------------------------------------------------------
#define WT_STRIDE 72
__global__ void k1p_mma(const float* __restrict__ X, int N) {
    extern __shared__ __half smh[];
    __half* Wt = smh;                    // [512][72]  (col, f)
    __half* Xs = smh + 512 * WT_STRIDE;  // [128][72]  (row, f)
    int t = threadIdx.x;

    // Stage WMt (fp32 [f][col]) -> Wt fp16 transposed [col][f]
    for (int i = t; i < 64 * 128; i += 256) {   // 64 f-rows x 128 float4
        int f = i >> 7, cq = i & 127;
        float4 v = ((const float4*)g_wmt)[f * 128 + cq];
        int col = cq * 4;
        Wt[(col + 0) * WT_STRIDE + f] = __float2half_rn(v.x);
        Wt[(col + 1) * WT_STRIDE + f] = __float2half_rn(v.y);
        Wt[(col + 2) * WT_STRIDE + f] = __float2half_rn(v.z);
        Wt[(col + 3) * WT_STRIDE + f] = __float2half_rn(v.w);
    }
    __syncthreads();

    int w = t >> 5, lane = t & 31;
    int g = lane >> 2, tig = lane & 3;   // groupID, threadID-in-group
    int r0 = w * 16;

    int nChunks = (N + 127) >> 7;
    for (int ch = blockIdx.x; ch < nChunks; ch += gridDim.x) {
        int n0 = ch << 7;
        // Stage X chunk fp32 -> fp16 (zero-padded for tail rows)
        for (int i = t; i < 2048; i += 256) {    // 128 rows x 16 float4
            int r = i >> 4, q = i & 15;
            float4 v = make_float4(0.f, 0.f, 0.f, 0.f);
            if (n0 + r < N) v = ((const float4*)X)[(size_t)(n0 + r) * 16 + q];
            *(__half2*)&Xs[r * WT_STRIDE + q * 4]     = __floats2half2_rn(v.x, v.y);
            *(__half2*)&Xs[r * WT_STRIDE + q * 4 + 2] = __floats2half2_rn(v.z, v.w);
        }
        __syncthreads();

        #pragma unroll 1
        for (int j = 0; j < 8; j++) {
            float c[8][4];
            #pragma unroll
            for (int s = 0; s < 8; s++)
                #pragma unroll
                for (int q = 0; q < 4; q++) c[s][q] = 0.f;

            #pragma unroll
            for (int kk = 0; kk < 4; kk++) {
                int k0 = kk * 16;
                // A fragment (16x16): rows r0+g / r0+g+8, cols k0+2tig(+8)
                unsigned a0 = *(const unsigned*)&Xs[(r0 + g)     * WT_STRIDE + k0 + 2 * tig];
                unsigned a1 = *(const unsigned*)&Xs[(r0 + g + 8) * WT_STRIDE + k0 + 2 * tig];
                unsigned a2 = *(const unsigned*)&Xs[(r0 + g)     * WT_STRIDE + k0 + 8 + 2 * tig];
                unsigned a3 = *(const unsigned*)&Xs[(r0 + g + 8) * WT_STRIDE + k0 + 8 + 2 * tig];
                #pragma unroll
                for (int s = 0; s < 8; s++) {
                    int col = j * 64 + s * 8 + g;
                    unsigned b0 = *(const unsigned*)&Wt[col * WT_STRIDE + k0 + 2 * tig];
                    unsigned b1 = *(const unsigned*)&Wt[col * WT_STRIDE + k0 + 8 + 2 * tig];
                    asm volatile(
                        "mma.sync.aligned.m16n8k16.row.col.f32.f16.f16.f32 "
                        "{%0,%1,%2,%3}, {%4,%5,%6,%7}, {%8,%9}, {%0,%1,%2,%3};"
                        : "+f"(c[s][0]), "+f"(c[s][1]), "+f"(c[s][2]), "+f"(c[s][3])
                        : "r"(a0), "r"(a1), "r"(a2), "r"(a3), "r"(b0), "r"(b1));
                }
            }
            // Store C: (row g, cols 2tig..) and (row g+8, same cols)
            int r_lo = n0 + r0 + g;
            int r_hi = r_lo + 8;
            #pragma unroll
            for (int s = 0; s < 8; s++) {
                int col = j * 64 + s * 8 + 2 * tig;
                if (r_lo < N)
                    *(__half2*)&g_ph[(size_t)r_lo * 512 + col] = __floats2half2_rn(c[s][0], c[s][1]);
                if (r_hi < N)
                    *(__half2*)&g_ph[(size_t)r_hi * 512 + col] = __floats2half2_rn(c[s][2], c[s][3]);
            }
        }
        __syncthreads();
    }
}

// ---------------------------------------------------------------------------
// K2N: fused attention + aggregation + merge. fp16 p gathers. (unchanged)
// ---------------------------------------------------------------------------
__global__ void k2n(const int* __restrict__ edges, float* __restrict__ out, int N) {
    __shared__ float asrc[8];
    __shared__ float attsum[8];
    __shared__ float inv_s[8];
    __shared__ float att_s[DEGCAP * 8];
    __shared__ int   dst_s[DEGCAP];

    int n = blockIdx.x;
    int t = threadIdx.x;
    int start = g_rowptr[n], end = g_rowptr[n + 1];
    int deg = end - start;

    if (t < 8) { asrc[t] = g_asrc[n * 8 + t]; attsum[t] = 0.f; }
    __syncthreads();

    float4 acc = make_float4(0.f, 0.f, 0.f, 0.f);
    int hb = t & 1;
    int ei = t >> 3, hh = t & 7;

    if (deg <= DEGCAP) {
        float psum = 0.f;
        for (int e0 = 0; e0 < deg; e0 += 16) {
            bool valid = (e0 + ei) < deg;
            float av = 0.f;
            if (valid) {
                int d = edges[2 * (start + e0 + ei) + 1];
                if (hh == 0) dst_s[e0 + ei] = d;
                float s = asrc[hh] + g_adst[d * 8 + hh];
                s = s > 0.f ? s : NEG_SLOPE * s;
                s = fminf(2.f, fmaxf(-2.f, s));
                av = __expf(s);
                att_s[(e0 + ei) * 8 + hh] = av;
            }
            psum += av;
        }
        psum += __shfl_down_sync(0xffffffffu, psum, 16);
        psum += __shfl_down_sync(0xffffffffu, psum, 8);
        if ((t & 31) < 8) atomicAdd(&attsum[hh], psum);
        __syncthreads();
        if (t < 8) inv_s[t] = attsum[t] > 0.f ? 1.f / attsum[t] : 0.f;
        __syncthreads();
        for (int i = t; i < deg * 8; i += 128) att_s[i] *= inv_s[i & 7];
        __syncthreads();

        #pragma unroll 4
        for (int i = 0; i < deg; i++) {
            float4 a4 = ((const float4*)att_s)[i * 2 + hb];
            uint2 pv = ((const uint2*)g_ph)[(size_t)dst_s[i] * 128 + t];
            float2 f01 = __half22float2(*(__half2*)&pv.x);
            float2 f23 = __half22float2(*(__half2*)&pv.y);
            acc.x = fmaf(a4.x, f01.x, acc.x);
            acc.y = fmaf(a4.y, f01.y, acc.y);
            acc.z = fmaf(a4.z, f23.x, acc.z);
            acc.w = fmaf(a4.w, f23.y, acc.w);
        }
    } else {
        // Rare fallback (deg > DEGCAP)
        float psum = 0.f;
        for (int e0 = 0; e0 < deg; e0 += 16) {
            bool valid = (e0 + ei) < deg;
            float av = 0.f;
            if (valid) {
                int d = edges[2 * (start + e0 + ei) + 1];
                float s = asrc[hh] + g_adst[d * 8 + hh];
                s = s > 0.f ? s : NEG_SLOPE * s;
                s = fminf(2.f, fmaxf(-2.f, s));
                av = __expf(s);
            }
            psum += av;
        }
        psum += __shfl_down_sync(0xffffffffu, psum, 16);
        psum += __shfl_down_sync(0xffffffffu, psum, 8);
        if ((t & 31) < 8) atomicAdd(&attsum[hh], psum);
        __syncthreads();
        if (t < 8) inv_s[t] = attsum[t] > 0.f ? 1.f / attsum[t] : 0.f;
        __syncthreads();

        for (int e0 = 0; e0 < deg; e0 += 16) {
            int cnt = min(16, deg - e0);
            if (t < cnt * 8) {
                int d = edges[2 * (start + e0 + ei) + 1];
                if (hh == 0) dst_s[ei] = d;
                float s = asrc[hh] + g_adst[d * 8 + hh];
                s = s > 0.f ? s : NEG_SLOPE * s;
                s = fminf(2.f, fmaxf(-2.f, s));
                att_s[ei * 8 + hh] = __expf(s) * inv_s[hh];
            }
            __syncthreads();
            #pragma unroll 2
            for (int i = 0; i < cnt; i++) {
                float4 a4 = ((const float4*)att_s)[i * 2 + hb];
                uint2 pv = ((const uint2*)g_ph)[(size_t)dst_s[i] * 128 + t];
                float2 f01 = __half22float2(*(__half2*)&pv.x);
                float2 f23 = __half22float2(*(__half2*)&pv.y);
                acc.x = fmaf(a4.x, f01.x, acc.x);
                acc.y = fmaf(a4.y, f01.y, acc.y);
                acc.z = fmaf(a4.z, f23.x, acc.z);
                acc.w = fmaf(a4.w, f23.y, acc.w);
            }
            __syncthreads();
        }
    }

    float v = acc.x + acc.y + acc.z + acc.w;
    v += __shfl_xor_sync(0xffffffffu, v, 1);
    if ((t & 1) == 0) {
        int c = t >> 1;
        out[(size_t)n * 64 + c] = v > 0.f ? v : NEG_SLOPE * v;
    }
}

// ---------------------------------------------------------------------------
extern "C" void kernel_launch(void* const* d_in, const int* in_sizes, int n_in,
                              void* d_out, int out_size) {
    const float* X  = (const float*)d_in[0];   // atom_features (N,64)
    const int*   Ed = (const int*)d_in[1];     // edges (E,2)
    const float* W  = (const float*)d_in[2];   // (8,64,64)
    const float* A  = (const float*)d_in[3];   // (8,128,1)
    const float* M  = (const float*)d_in[4];   // (512,64)
    float* out = (float*)d_out;                // (N,64)

    int N = in_sizes[0] / 64;
    int E = in_sizes[1] / 2;

    static bool attr_set = false;
    if (!attr_set) {
        cudaFuncSetAttribute(k1p_mma, cudaFuncAttributeMaxDynamicSharedMemorySize,
                             (512 + 128) * WT_STRIDE * (int)sizeof(__half));
        attr_set = true;
    }

    k0_rowptr<<<(N + 1 + 255) / 256, 256>>>(Ed, N, E);
    kpre<<<132, 256>>>(W, A, M);
    kalpha<<<(N + 15) / 16, 256>>>(X, N);
    k1p_mma<<<296, 256, (512 + 128) * WT_STRIDE * sizeof(__half)>>>(X, N);
    k2n<<<N, 128>>>(Ed, out, N);
}